// round 16
// baseline (speedup 1.0000x reference)
#include <cuda_runtime.h>
#include <cuda_bf16.h>
#include <cstdint>

// Problem constants
#define BATCH 16
#define SEQ   1024
#define T     (BATCH * SEQ)      // 16384 serial steps per chain
#define HID   600
#define IN    512                // 3 (tag emb) + 509 (context)
#define G3    1800               // 3*HID

// Recurrence config: 2 groups x 60 blocks. Each group covers ALL 600 hidden
// indices and alternates chains each phase. Synchronization is data-driven:
// h travels as {step-tag, value} 8-byte pairs; staging self-validates.
#define GBLK  60                 // blocks per group
#define NBLK  (2 * GBLK)         // total persistent blocks
#define IPB   10                 // hidden indices per block (GBLK*IPB = 600)
#define RTHREADS 320             // 10 warps, one hidden index each

// ------------------- static device scratch (no allocations allowed) -------
__device__ float              d_X[(size_t)T * IN];    // 33.5 MB built input
__device__ float              d_gx[(size_t)T * G3];   // 118 MB precomputed gates
// h as {tag<<32 | value-bits} pairs: [chain][parity][slot], slot padded to 640
__device__ unsigned long long d_hp[2][2][640];

// ------------------- relaxed 64-bit helpers (L2, no fences) ----------------
__device__ __forceinline__ unsigned long long ld_rlx64(const unsigned long long* p) {
    unsigned long long v;
    asm volatile("ld.relaxed.gpu.global.b64 %0, [%1];" : "=l"(v) : "l"(p) : "memory");
    return v;
}
__device__ __forceinline__ void st_rlx64(unsigned long long* p, unsigned long long v) {
    asm volatile("st.relaxed.gpu.global.b64 [%0], %1;" :: "l"(p), "l"(v) : "memory");
}
__device__ __forceinline__ float sigm(float x) {
    return 1.0f / (1.0f + __expf(-x));
}
__device__ __forceinline__ float tanh_fast(float x) {
    x = fminf(15.0f, fmaxf(-15.0f, x));
    float e = __expf(2.0f * x);
    return __fdividef(e - 1.0f, e + 1.0f);
}

// ------------------- kernel 0: init h pair buffers --------------------------
// buffer[0] = {tag 0, 0.0f} = valid step-0 state; buffer[1] zero tags never
// match its first expected tag (1), so zero-init is safe for both.
__global__ void init_bufs() {
    int t = threadIdx.x + blockIdx.x * blockDim.x;
    if (t < 2 * 2 * 640) ((unsigned long long*)d_hp)[t] = 0ull;
}

// ------------------- kernel 1: build X = [tag_emb(tags), context] ---------
__global__ void build_x(const float* __restrict__ ctx,
                        const int* __restrict__ tags,
                        const float* __restrict__ emb) {
    int t = blockIdx.x;        // 0..16383
    int k = threadIdx.x;       // 0..511
    float v;
    if (k < 3) v = emb[tags[t] * 3 + k];
    else       v = ctx[(size_t)t * 509 + (k - 3)];
    d_X[(size_t)t * IN + k] = v;
}

// ------------------- kernel 2: gx = X @ W_ih^T + b_ih ---------------------
#define BM 128
#define BN 128
#define BKK 16
__global__ __launch_bounds__(256) void gemm_gx(const float* __restrict__ Wih,
                                               const float* __restrict__ bih) {
    __shared__ float As[BKK][BM];
    __shared__ float Bs[BKK][BN];
    int tid = threadIdx.x;
    int bm = blockIdx.x * BM;
    int bn = blockIdx.y * BN;
    int tx = tid & 15;
    int ty = tid >> 4;
    float acc[8][8];
#pragma unroll
    for (int r = 0; r < 8; r++)
#pragma unroll
        for (int c = 0; c < 8; c++) acc[r][c] = 0.0f;

    for (int k0 = 0; k0 < IN; k0 += BKK) {
#pragma unroll
        for (int i = 0; i < 2; i++) {
            int id = tid + i * 256;
            int m  = id >> 2;
            int kq = (id & 3) * 4;
            float4 v = *(const float4*)&d_X[(size_t)(bm + m) * IN + k0 + kq];
            As[kq + 0][m] = v.x; As[kq + 1][m] = v.y;
            As[kq + 2][m] = v.z; As[kq + 3][m] = v.w;
        }
#pragma unroll
        for (int i = 0; i < 2; i++) {
            int id = tid + i * 256;
            int n  = id >> 2;
            int kq = (id & 3) * 4;
            int j  = bn + n;
            float4 v = make_float4(0.f, 0.f, 0.f, 0.f);
            if (j < G3) v = *(const float4*)&Wih[(size_t)j * IN + k0 + kq];
            Bs[kq + 0][n] = v.x; Bs[kq + 1][n] = v.y;
            Bs[kq + 2][n] = v.z; Bs[kq + 3][n] = v.w;
        }
        __syncthreads();
#pragma unroll
        for (int kk = 0; kk < BKK; kk++) {
            float a[8], b[8];
#pragma unroll
            for (int u = 0; u < 4; u++) {
                a[u]     = As[kk][ty * 4 + u];
                a[4 + u] = As[kk][64 + ty * 4 + u];
                b[u]     = Bs[kk][tx * 4 + u];
                b[4 + u] = Bs[kk][64 + tx * 4 + u];
            }
#pragma unroll
            for (int r = 0; r < 8; r++)
#pragma unroll
                for (int c = 0; c < 8; c++) acc[r][c] += a[r] * b[c];
        }
        __syncthreads();
    }
#pragma unroll
    for (int r = 0; r < 8; r++) {
        int m = bm + ((r < 4) ? (ty * 4 + r) : (64 + ty * 4 + (r - 4)));
#pragma unroll
        for (int c = 0; c < 8; c++) {
            int j = bn + ((c < 4) ? (tx * 4 + c) : (64 + tx * 4 + (c - 4)));
            if (j < G3)
                d_gx[(size_t)m * G3 + j] = acc[r][c] + __ldg(&bih[j]);
        }
    }
}

// ------------------- phase body: one chain-step of chain c at phase p -----
__device__ __forceinline__ void gru_phase(
    int p, int c, int i, int tid, int lane,
    const float* wr, const float* wz, const float* wn,
    float bhr, float bhz, float bhn,
    float& pg0, float& pg1, float& pg2,
    float* s_h, float* __restrict__ out)
{
    // lane 0: consume this phase's gates, prefetch this chain's step p+2
    // (handled by this same group) — issued before staging.
    float g0 = 0.f, g1 = 0.f, g2 = 0.f;
    if (lane == 0) {
        g0 = pg0; g1 = pg1; g2 = pg2;
        int sn = p + 2;
        if (sn < T) {
            int row = c ? (sn + 1023 - 2 * (sn & 1023)) : sn;
            const float* gp = &d_gx[(size_t)row * G3];
            pg0 = __ldcg(gp + i);
            pg1 = __ldcg(gp + HID + i);
            pg2 = __ldcg(gp + 2 * HID + i);
        }
    }

    // ---- self-validating staging: each thread owns 2 tagged pairs ----
    {
        const unsigned long long* src = d_hp[c][p & 1];
        unsigned exp = (unsigned)p;
        int i0 = tid * 2;
        int i1 = i0 + 1;
        bool need0 = (i0 < HID), need1 = (i1 < HID);
        unsigned long long v0 = ld_rlx64(&src[i0]);
        unsigned long long v1 = ld_rlx64(&src[i1]);
        bool ok0 = !need0 || ((unsigned)(v0 >> 32) == exp);
        bool ok1 = !need1 || ((unsigned)(v1 >> 32) == exp);
        while (!(ok0 && ok1)) {
            __nanosleep(64);     // backoff: keep retry pressure off the lines
            if (!ok0) { v0 = ld_rlx64(&src[i0]); ok0 = ((unsigned)(v0 >> 32) == exp); }
            if (!ok1) { v1 = ld_rlx64(&src[i1]); ok1 = ((unsigned)(v1 >> 32) == exp); }
        }
        s_h[i0] = need0 ? __uint_as_float((unsigned)v0) : 0.0f;
        s_h[i1] = need1 ? __uint_as_float((unsigned)v1) : 0.0f;
    }
    __syncthreads();

    // ---- dot products from SMEM ----
    float a = 0.f, z = 0.f, n = 0.f;
#pragma unroll
    for (int cc = 0; cc < 5; cc++) {
        float4 hv = *(const float4*)&s_h[cc * 128 + lane * 4];
        const float* WR = &wr[cc * 4];
        const float* WZ = &wz[cc * 4];
        const float* WN = &wn[cc * 4];
        a += WR[0] * hv.x + WR[1] * hv.y + WR[2] * hv.z + WR[3] * hv.w;
        z += WZ[0] * hv.x + WZ[1] * hv.y + WZ[2] * hv.z + WZ[3] * hv.w;
        n += WN[0] * hv.x + WN[1] * hv.y + WN[2] * hv.z + WN[3] * hv.w;
    }
#pragma unroll
    for (int o = 16; o; o >>= 1) {
        a += __shfl_down_sync(0xffffffffu, a, o);
        z += __shfl_down_sync(0xffffffffu, z, o);
        n += __shfl_down_sync(0xffffffffu, n, o);
    }

    if (lane == 0) {
        float hi = s_h[i];
        float r_ = sigm(g0 + a + bhr);
        float z_ = sigm(g1 + z + bhz);
        float n_ = tanh_fast(g2 + r_ * (n + bhn));
        float hn = (1.0f - z_) * n_ + z_ * hi;
        // publish {tag p+1, value}: the data IS the flag
        unsigned long long pk =
            ((unsigned long long)(unsigned)(p + 1) << 32) |
            (unsigned long long)__float_as_uint(hn);
        st_rlx64(&d_hp[c][(p + 1) & 1][i], pk);
        if (p == T - 1) out[c * HID + i] = hn;
    }

    __syncthreads();   // all warps done with s_h before next phase reuses it
}

// ------------------- kernel 3: interleaved dual-chain GRU recurrence ------
// Group 0 = blocks [0,60), group 1 = blocks [60,120). Each group covers all
// 600 hidden indices. Phase p: group g computes chain c = (p&1)^g, step p,
// consuming the other group's previous-phase tagged output pairs.
__global__ void __launch_bounds__(RTHREADS, 1)
gru_recur(const float* __restrict__ Whh,
          const float* __restrict__ bhh,
          float* __restrict__ out) {
    __shared__ __align__(16) float s_h[640];

    int tid  = threadIdx.x;
    int w    = tid >> 5;
    int lane = tid & 31;
    int g    = (blockIdx.x < GBLK) ? 0 : 1;     // group
    int blkl = blockIdx.x - g * GBLK;
    int i    = blkl * IPB + w;                  // this warp's hidden index
    int cE   = g;                               // chain on even phases
    int cO   = 1 - g;                           // chain on odd phases

    // --- load this warp's W_hh rows into registers (zero-padded) ---
    float wr[20], wz[20], wn[20];
#pragma unroll
    for (int c = 0; c < 5; c++) {
#pragma unroll
        for (int u = 0; u < 4; u++) {
            int k = c * 128 + lane * 4 + u;
            bool ok = (k < HID);
            wr[c * 4 + u] = ok ? Whh[(size_t)(0 * HID + i) * HID + k] : 0.0f;
            wz[c * 4 + u] = ok ? Whh[(size_t)(1 * HID + i) * HID + k] : 0.0f;
            wn[c * 4 + u] = ok ? Whh[(size_t)(2 * HID + i) * HID + k] : 0.0f;
        }
    }
    float bhr = 0.f, bhz = 0.f, bhn = 0.f;
    if (lane == 0) {
        bhr = bhh[i];
        bhz = bhh[HID + i];
        bhn = bhh[2 * HID + i];
    }

    // --- initial gx prefetch: even-chain step 0, odd-chain step 1 ---
    float pgE0 = 0.f, pgE1 = 0.f, pgE2 = 0.f;
    float pgO0 = 0.f, pgO1 = 0.f, pgO2 = 0.f;
    if (lane == 0) {
        int rowE = cE ? 1023 : 0;                 // chain cE, step 0
        int rowO = cO ? 1022 : 1;                 // chain cO, step 1
        const float* gE = &d_gx[(size_t)rowE * G3];
        const float* gO = &d_gx[(size_t)rowO * G3];
        pgE0 = __ldcg(gE + i); pgE1 = __ldcg(gE + HID + i); pgE2 = __ldcg(gE + 2 * HID + i);
        pgO0 = __ldcg(gO + i); pgO1 = __ldcg(gO + HID + i); pgO2 = __ldcg(gO + 2 * HID + i);
    }

    for (int p = 0; p < T; p += 2) {
        gru_phase(p,     cE, i, tid, lane, wr, wz, wn, bhr, bhz, bhn,
                  pgE0, pgE1, pgE2, s_h, out);
        gru_phase(p + 1, cO, i, tid, lane, wr, wz, wn, bhr, bhz, bhn,
                  pgO0, pgO1, pgO2, s_h, out);
    }
}

// ------------------- launch ------------------------------------------------
extern "C" void kernel_launch(void* const* d_in, const int* in_sizes, int n_in,
                              void* d_out, int out_size) {
    const float* context = (const float*)d_in[0];   // [16,1024,509]
    const int*   tags    = (const int*)  d_in[1];   // [16,1024]
    const float* tag_emb = (const float*)d_in[2];   // [3,3]
    const float* W_ih    = (const float*)d_in[3];   // [1800,512]
    const float* W_hh    = (const float*)d_in[4];   // [1800,600]
    const float* b_ih    = (const float*)d_in[5];   // [1800]
    const float* b_hh    = (const float*)d_in[6];   // [1800]
    float*       out     = (float*)d_out;           // [1200]

    init_bufs<<<4, 640>>>();
    build_x<<<T, IN>>>(context, tags, tag_emb);
    dim3 g((T + BM - 1) / BM, (G3 + BN - 1) / BN);  // 128 x 15
    gemm_gx<<<g, 256>>>(W_ih, b_ih);
    gru_recur<<<NBLK, RTHREADS>>>(W_hh, b_hh, out);
}

// round 17
// speedup vs baseline: 1.1399x; 1.1399x over previous
#include <cuda_runtime.h>
#include <cuda_bf16.h>
#include <cstdint>

// Problem constants
#define BATCH 16
#define SEQ   1024
#define T     (BATCH * SEQ)      // 16384 serial steps per chain
#define HID   600
#define IN    512                // 3 (tag emb) + 509 (context)
#define G3    1800               // 3*HID

// Recurrence config: 2 groups x 40 blocks, 15 warps each (one hidden index
// per warp, per-warp work unchanged). Interleaved dual-chain (r15) with the
// r13 barrier. Fewer participants => less arrival serialization, less
// h-line read fan-out, smaller max-of-N jitter.
#define GBLK  40                 // blocks per group (= arrivals per chain-step)
#define NBLK  (2 * GBLK)         // total persistent blocks
#define IPB   15                 // hidden indices per block (GBLK*IPB = 600)
#define RTHREADS 480             // 15 warps, one hidden index each
#define H4    160                // 640 floats = 160 float4 per h buffer

// ------------------- static device scratch (no allocations allowed) -------
__device__ float    d_X[(size_t)T * IN];        // 33.5 MB  built input
__device__ float    d_gx[(size_t)T * G3];       // 118 MB   precomputed gates
__device__ __align__(16) float d_h[2][2][640];  // [chain][parity][slot]
__device__ unsigned d_count[2][32];             // per-chain arrival counter

// ------------------- memory-order helpers (r13 frozen barrier) -------------
__device__ __forceinline__ unsigned ld_rlx(const unsigned* p) {
    unsigned v;
    asm volatile("ld.relaxed.gpu.global.b32 %0, [%1];" : "=r"(v) : "l"(p) : "memory");
    return v;
}
__device__ __forceinline__ void red_rel_add(unsigned* p, unsigned v) {
    asm volatile("red.release.gpu.global.add.u32 [%0], %1;" :: "l"(p), "r"(v) : "memory");
}
__device__ __forceinline__ void fence_ar_gpu() {
    asm volatile("fence.acq_rel.gpu;" ::: "memory");
}
__device__ __forceinline__ float sigm(float x) {
    return 1.0f / (1.0f + __expf(-x));
}
__device__ __forceinline__ float tanh_fast(float x) {
    x = fminf(15.0f, fmaxf(-15.0f, x));
    float e = __expf(2.0f * x);
    return __fdividef(e - 1.0f, e + 1.0f);
}

// ------------------- kernel 0: init barrier + h buffers -------------------
__global__ void init_bufs() {
    int t = threadIdx.x + blockIdx.x * blockDim.x;
    float* h = (float*)d_h;
    if (t < 2 * 2 * 640) h[t] = 0.0f;
    if (t < 2) d_count[t][0] = 0u;
}

// ------------------- kernel 1: build X = [tag_emb(tags), context] ---------
__global__ void build_x(const float* __restrict__ ctx,
                        const int* __restrict__ tags,
                        const float* __restrict__ emb) {
    int t = blockIdx.x;        // 0..16383
    int k = threadIdx.x;       // 0..511
    float v;
    if (k < 3) v = emb[tags[t] * 3 + k];
    else       v = ctx[(size_t)t * 509 + (k - 3)];
    d_X[(size_t)t * IN + k] = v;
}

// ------------------- kernel 2: gx = X @ W_ih^T + b_ih ---------------------
#define BM 128
#define BN 128
#define BKK 16
__global__ __launch_bounds__(256) void gemm_gx(const float* __restrict__ Wih,
                                               const float* __restrict__ bih) {
    __shared__ float As[BKK][BM];
    __shared__ float Bs[BKK][BN];
    int tid = threadIdx.x;
    int bm = blockIdx.x * BM;
    int bn = blockIdx.y * BN;
    int tx = tid & 15;
    int ty = tid >> 4;
    float acc[8][8];
#pragma unroll
    for (int r = 0; r < 8; r++)
#pragma unroll
        for (int c = 0; c < 8; c++) acc[r][c] = 0.0f;

    for (int k0 = 0; k0 < IN; k0 += BKK) {
#pragma unroll
        for (int i = 0; i < 2; i++) {
            int id = tid + i * 256;
            int m  = id >> 2;
            int kq = (id & 3) * 4;
            float4 v = *(const float4*)&d_X[(size_t)(bm + m) * IN + k0 + kq];
            As[kq + 0][m] = v.x; As[kq + 1][m] = v.y;
            As[kq + 2][m] = v.z; As[kq + 3][m] = v.w;
        }
#pragma unroll
        for (int i = 0; i < 2; i++) {
            int id = tid + i * 256;
            int n  = id >> 2;
            int kq = (id & 3) * 4;
            int j  = bn + n;
            float4 v = make_float4(0.f, 0.f, 0.f, 0.f);
            if (j < G3) v = *(const float4*)&Wih[(size_t)j * IN + k0 + kq];
            Bs[kq + 0][n] = v.x; Bs[kq + 1][n] = v.y;
            Bs[kq + 2][n] = v.z; Bs[kq + 3][n] = v.w;
        }
        __syncthreads();
#pragma unroll
        for (int kk = 0; kk < BKK; kk++) {
            float a[8], b[8];
#pragma unroll
            for (int u = 0; u < 4; u++) {
                a[u]     = As[kk][ty * 4 + u];
                a[4 + u] = As[kk][64 + ty * 4 + u];
                b[u]     = Bs[kk][tx * 4 + u];
                b[4 + u] = Bs[kk][64 + tx * 4 + u];
            }
#pragma unroll
            for (int r = 0; r < 8; r++)
#pragma unroll
                for (int c = 0; c < 8; c++) acc[r][c] += a[r] * b[c];
        }
        __syncthreads();
    }
#pragma unroll
    for (int r = 0; r < 8; r++) {
        int m = bm + ((r < 4) ? (ty * 4 + r) : (64 + ty * 4 + (r - 4)));
#pragma unroll
        for (int c = 0; c < 8; c++) {
            int j = bn + ((c < 4) ? (tx * 4 + c) : (64 + tx * 4 + (c - 4)));
            if (j < G3)
                d_gx[(size_t)m * G3 + j] = acc[r][c] + __ldg(&bih[j]);
        }
    }
}

// ------------------- phase body: one chain-step of chain c at phase p -----
__device__ __forceinline__ void gru_phase(
    int p, int c, int i, int tid, int lane,
    const float* wr, const float* wz, const float* wn,
    float bhr, float bhz, float bhn,
    float& pg0, float& pg1, float& pg2,
    float* s_h, float* __restrict__ out)
{
    // lane 0: consume this phase's gates, prefetch this chain's step p+2
    float g0 = 0.f, g1 = 0.f, g2 = 0.f;
    if (lane == 0) {
        g0 = pg0; g1 = pg1; g2 = pg2;
        int sn = p + 2;
        if (sn < T) {
            int row = c ? (sn + 1023 - 2 * (sn & 1023)) : sn;
            const float* gp = &d_gx[(size_t)row * G3];
            pg0 = __ldcg(gp + i);
            pg1 = __ldcg(gp + HID + i);
            pg2 = __ldcg(gp + 2 * HID + i);
        }
    }

    // wait for h_c(p): produced by the other group during our previous phase
    unsigned* cnt = &d_count[c][0];
    if (tid == 0 && p > 0) {
        unsigned tgt = (unsigned)p * GBLK;
        while (ld_rlx(cnt) < tgt) { }
        fence_ar_gpu();
    }
    __syncthreads();

    // stage h_c(p) into SMEM (160 float4)
    if (tid < H4) {
        const float4* h4 = (const float4*)d_h[c][p & 1];
        ((float4*)s_h)[tid] = __ldcg(&h4[tid]);
    }
    __syncthreads();

    // dot products from SMEM
    float a = 0.f, z = 0.f, n = 0.f;
#pragma unroll
    for (int cc = 0; cc < 5; cc++) {
        float4 hv = *(const float4*)&s_h[cc * 128 + lane * 4];
        const float* WR = &wr[cc * 4];
        const float* WZ = &wz[cc * 4];
        const float* WN = &wn[cc * 4];
        a += WR[0] * hv.x + WR[1] * hv.y + WR[2] * hv.z + WR[3] * hv.w;
        z += WZ[0] * hv.x + WZ[1] * hv.y + WZ[2] * hv.z + WZ[3] * hv.w;
        n += WN[0] * hv.x + WN[1] * hv.y + WN[2] * hv.z + WN[3] * hv.w;
    }
#pragma unroll
    for (int o = 16; o; o >>= 1) {
        a += __shfl_down_sync(0xffffffffu, a, o);
        z += __shfl_down_sync(0xffffffffu, z, o);
        n += __shfl_down_sync(0xffffffffu, n, o);
    }

    if (lane == 0) {
        float hi = s_h[i];
        float r_ = sigm(g0 + a + bhr);
        float z_ = sigm(g1 + z + bhz);
        float n_ = tanh_fast(g2 + r_ * (n + bhn));
        float hn = (1.0f - z_) * n_ + z_ * hi;
        d_h[c][(p + 1) & 1][i] = hn;
        if (p == T - 1) out[c * HID + i] = hn;
    }

    __syncthreads();                  // all warps done with s_h + h stores
    if (tid == 0) red_rel_add(cnt, 1u);   // release arrival (fire-and-forget)
}

// ------------------- kernel 3: interleaved dual-chain GRU recurrence ------
// Group 0 = blocks [0,40), group 1 = blocks [40,80). Each group covers all
// 600 hidden indices (15 warps x 40 blocks). Phase p: group g computes
// chain c = (p&1)^g, step p, consuming the other group's previous output.
__global__ void __launch_bounds__(RTHREADS, 1)
gru_recur(const float* __restrict__ Whh,
          const float* __restrict__ bhh,
          float* __restrict__ out) {
    __shared__ __align__(16) float s_h[640];

    int tid  = threadIdx.x;
    int w    = tid >> 5;
    int lane = tid & 31;
    int g    = (blockIdx.x < GBLK) ? 0 : 1;     // group
    int blkl = blockIdx.x - g * GBLK;
    int i    = blkl * IPB + w;                  // this warp's hidden index
    int cE   = g;                               // chain on even phases
    int cO   = 1 - g;                           // chain on odd phases

    // --- load this warp's W_hh rows into registers (zero-padded) ---
    float wr[20], wz[20], wn[20];
#pragma unroll
    for (int c = 0; c < 5; c++) {
#pragma unroll
        for (int u = 0; u < 4; u++) {
            int k = c * 128 + lane * 4 + u;
            bool ok = (k < HID);
            wr[c * 4 + u] = ok ? Whh[(size_t)(0 * HID + i) * HID + k] : 0.0f;
            wz[c * 4 + u] = ok ? Whh[(size_t)(1 * HID + i) * HID + k] : 0.0f;
            wn[c * 4 + u] = ok ? Whh[(size_t)(2 * HID + i) * HID + k] : 0.0f;
        }
    }
    float bhr = 0.f, bhz = 0.f, bhn = 0.f;
    if (lane == 0) {
        bhr = bhh[i];
        bhz = bhh[HID + i];
        bhn = bhh[2 * HID + i];
    }

    // --- initial gx prefetch: even-chain step 0, odd-chain step 1 ---
    float pgE0 = 0.f, pgE1 = 0.f, pgE2 = 0.f;
    float pgO0 = 0.f, pgO1 = 0.f, pgO2 = 0.f;
    if (lane == 0) {
        int rowE = cE ? 1023 : 0;                 // chain cE, step 0
        int rowO = cO ? 1022 : 1;                 // chain cO, step 1
        const float* gE = &d_gx[(size_t)rowE * G3];
        const float* gO = &d_gx[(size_t)rowO * G3];
        pgE0 = __ldcg(gE + i); pgE1 = __ldcg(gE + HID + i); pgE2 = __ldcg(gE + 2 * HID + i);
        pgO0 = __ldcg(gO + i); pgO1 = __ldcg(gO + HID + i); pgO2 = __ldcg(gO + 2 * HID + i);
    }

    for (int p = 0; p < T; p += 2) {
        gru_phase(p,     cE, i, tid, lane, wr, wz, wn, bhr, bhz, bhn,
                  pgE0, pgE1, pgE2, s_h, out);
        gru_phase(p + 1, cO, i, tid, lane, wr, wz, wn, bhr, bhz, bhn,
                  pgO0, pgO1, pgO2, s_h, out);
    }
}

// ------------------- launch ------------------------------------------------
extern "C" void kernel_launch(void* const* d_in, const int* in_sizes, int n_in,
                              void* d_out, int out_size) {
    const float* context = (const float*)d_in[0];   // [16,1024,509]
    const int*   tags    = (const int*)  d_in[1];   // [16,1024]
    const float* tag_emb = (const float*)d_in[2];   // [3,3]
    const float* W_ih    = (const float*)d_in[3];   // [1800,512]
    const float* W_hh    = (const float*)d_in[4];   // [1800,600]
    const float* b_ih    = (const float*)d_in[5];   // [1800]
    const float* b_hh    = (const float*)d_in[6];   // [1800]
    float*       out     = (float*)d_out;           // [1200]

    init_bufs<<<4, 640>>>();
    build_x<<<T, IN>>>(context, tags, tag_emb);
    dim3 g((T + BM - 1) / BM, (G3 + BN - 1) / BN);  // 128 x 15
    gemm_gx<<<g, 256>>>(W_ih, b_ih);
    gru_recur<<<NBLK, RTHREADS>>>(W_hh, b_hh, out);
}